// round 1
// baseline (speedup 1.0000x reference)
#include <cuda_runtime.h>
#include <math.h>

// Problem constants
#define B_   16
#define H_   56
#define W_   56
#define C_   512
#define WS_  7
#define NH_  16
#define HD_  32
#define HID_ 2048
#define N_   49
#define NW_  64
#define L_   (H_ * W_)          // 3136
#define ROWS_ (B_ * L_)         // 50176
#define SCALE_ 0.17677669529663687f
#define EPS_ 1e-5f

// Scratch (device globals: allocation-free)
__device__ float g_h [ROWS_ * C_];
__device__ float g_q [ROWS_ * C_];
__device__ float g_k [ROWS_ * C_];
__device__ float g_v [ROWS_ * C_];
__device__ float g_ao[ROWS_ * C_];
__device__ float g_x2[ROWS_ * C_];
__device__ float g_hid[ROWS_ * HID_];

// ---------------------------------------------------------------------------
// LayerNorm: one block per row of 512, 128 threads x float4
// ---------------------------------------------------------------------------
__global__ __launch_bounds__(128) void ln_kernel(const float* __restrict__ x,
                                                 const float* __restrict__ g,
                                                 const float* __restrict__ b,
                                                 float* __restrict__ out) {
    int row = blockIdx.x;
    const float4* xr = (const float4*)(x + (size_t)row * C_);
    float4 v = xr[threadIdx.x];
    float s  = v.x + v.y + v.z + v.w;
    float s2 = v.x * v.x + v.y * v.y + v.z * v.z + v.w * v.w;
    #pragma unroll
    for (int o = 16; o; o >>= 1) {
        s  += __shfl_xor_sync(0xffffffffu, s, o);
        s2 += __shfl_xor_sync(0xffffffffu, s2, o);
    }
    __shared__ float sm[4], sm2[4];
    int warp = threadIdx.x >> 5;
    if ((threadIdx.x & 31) == 0) { sm[warp] = s; sm2[warp] = s2; }
    __syncthreads();
    s  = sm[0] + sm[1] + sm[2] + sm[3];
    s2 = sm2[0] + sm2[1] + sm2[2] + sm2[3];
    float mu   = s * (1.0f / C_);
    float var  = s2 * (1.0f / C_) - mu * mu;
    float rstd = rsqrtf(var + EPS_);
    float4 gg = ((const float4*)g)[threadIdx.x];
    float4 bb = ((const float4*)b)[threadIdx.x];
    float4 o;
    o.x = (v.x - mu) * rstd * gg.x + bb.x;
    o.y = (v.y - mu) * rstd * gg.y + bb.y;
    o.z = (v.z - mu) * rstd * gg.z + bb.z;
    o.w = (v.w - mu) * rstd * gg.w + bb.w;
    ((float4*)(out + (size_t)row * C_))[threadIdx.x] = o;
}

// ---------------------------------------------------------------------------
// Generic fp32 GEMM: C[M,Nc] = A[M,K] @ B[K,Nc] + bias (+res) (gelu optional)
// BM=128, BN=64, BK=16, 256 threads, 8x4 per-thread tile, double buffered.
// ---------------------------------------------------------------------------
#define BM 128
#define BN 64
#define BK 16

__global__ __launch_bounds__(256, 2) void gemm_kernel(
    const float* __restrict__ A, const float* __restrict__ Bm,
    const float* __restrict__ bias, const float* __restrict__ res,
    float* __restrict__ C, int M, int Nc, int K, int do_gelu)
{
    __shared__ __align__(16) float As[2][BK][BM + 4];
    __shared__ __align__(16) float Bs[2][BK][BN];

    int tid = threadIdx.x;
    int tx = tid & 15;          // 16 col-groups of 4
    int ty = tid >> 4;          // 16 row-groups of 8
    int bm = blockIdx.y * BM;
    int bn = blockIdx.x * BN;

    // A tile: 128x16 = 512 float4, 2 per thread
    int af0 = tid, af1 = tid + 256;
    int ar0 = af0 >> 2, ak0 = (af0 & 3) * 4;
    int ar1 = af1 >> 2, ak1 = (af1 & 3) * 4;
    // B tile: 16x64 = 256 float4, 1 per thread
    int bkr = tid >> 4, bnc = (tid & 15) * 4;

    const float* Aptr = A + (size_t)bm * K;
    const float* Bptr = Bm + bn;

    float4 pa0 = *(const float4*)(Aptr + (size_t)ar0 * K + ak0);
    float4 pa1 = *(const float4*)(Aptr + (size_t)ar1 * K + ak1);
    float4 pb  = *(const float4*)(Bptr + (size_t)bkr * Nc + bnc);

    As[0][ak0 + 0][ar0] = pa0.x; As[0][ak0 + 1][ar0] = pa0.y;
    As[0][ak0 + 2][ar0] = pa0.z; As[0][ak0 + 3][ar0] = pa0.w;
    As[0][ak1 + 0][ar1] = pa1.x; As[0][ak1 + 1][ar1] = pa1.y;
    As[0][ak1 + 2][ar1] = pa1.z; As[0][ak1 + 3][ar1] = pa1.w;
    *(float4*)&Bs[0][bkr][bnc] = pb;
    __syncthreads();

    float acc[8][4];
    #pragma unroll
    for (int r = 0; r < 8; r++)
        #pragma unroll
        for (int c = 0; c < 4; c++) acc[r][c] = 0.0f;

    int nt = K / BK;
    for (int t = 0; t < nt; t++) {
        int cur = t & 1;
        if (t + 1 < nt) {
            int k0 = (t + 1) * BK;
            pa0 = *(const float4*)(Aptr + (size_t)ar0 * K + k0 + ak0);
            pa1 = *(const float4*)(Aptr + (size_t)ar1 * K + k0 + ak1);
            pb  = *(const float4*)(Bptr + (size_t)(k0 + bkr) * Nc + bnc);
        }
        #pragma unroll
        for (int kk = 0; kk < BK; kk++) {
            float4 a0  = *(const float4*)&As[cur][kk][ty * 8];
            float4 a1  = *(const float4*)&As[cur][kk][ty * 8 + 4];
            float4 bv4 = *(const float4*)&Bs[cur][kk][tx * 4];
            float av[8] = {a0.x, a0.y, a0.z, a0.w, a1.x, a1.y, a1.z, a1.w};
            float bv[4] = {bv4.x, bv4.y, bv4.z, bv4.w};
            #pragma unroll
            for (int r = 0; r < 8; r++)
                #pragma unroll
                for (int c = 0; c < 4; c++)
                    acc[r][c] = fmaf(av[r], bv[c], acc[r][c]);
        }
        if (t + 1 < nt) {
            int nb = 1 - cur;
            As[nb][ak0 + 0][ar0] = pa0.x; As[nb][ak0 + 1][ar0] = pa0.y;
            As[nb][ak0 + 2][ar0] = pa0.z; As[nb][ak0 + 3][ar0] = pa0.w;
            As[nb][ak1 + 0][ar1] = pa1.x; As[nb][ak1 + 1][ar1] = pa1.y;
            As[nb][ak1 + 2][ar1] = pa1.z; As[nb][ak1 + 3][ar1] = pa1.w;
            *(float4*)&Bs[nb][bkr][bnc] = pb;
        }
        __syncthreads();
    }

    float4 bias4 = *(const float4*)(bias + bn + tx * 4);
    #pragma unroll
    for (int r = 0; r < 8; r++) {
        size_t row = (size_t)(bm + ty * 8 + r);
        float4 o;
        o.x = acc[r][0] + bias4.x;
        o.y = acc[r][1] + bias4.y;
        o.z = acc[r][2] + bias4.z;
        o.w = acc[r][3] + bias4.w;
        if (res) {
            float4 rr = *(const float4*)(res + row * Nc + bn + tx * 4);
            o.x += rr.x; o.y += rr.y; o.z += rr.z; o.w += rr.w;
        }
        if (do_gelu) {
            o.x = o.x * normcdff(o.x);
            o.y = o.y * normcdff(o.y);
            o.z = o.z * normcdff(o.z);
            o.w = o.w * normcdff(o.w);
        }
        *(float4*)(C + row * Nc + bn + tx * 4) = o;
    }
}

// ---------------------------------------------------------------------------
// Fused window attention: one block per (window, head), 128 threads.
// Reads q/k/v in spatial (B,L,C) layout via window index mapping and writes
// the attention output back in spatial layout (window-reverse is free).
// ---------------------------------------------------------------------------
__global__ __launch_bounds__(128) void attn_kernel(
    const float* __restrict__ q, const float* __restrict__ k,
    const float* __restrict__ v, const float* __restrict__ rel_bias,
    float* __restrict__ ao)
{
    int w = blockIdx.x;          // 0..1023
    int head = blockIdx.y;       // 0..15
    int b  = w >> 6;
    int wi = w & 63;
    int wr = wi >> 3;
    int wc = wi & 7;
    int tid = threadIdx.x;

    __shared__ float qs[N_][HD_];     // [49][32]
    __shared__ float kT[HD_][N_];     // [32][49]
    __shared__ float vT[HD_][N_];     // [32][49]
    __shared__ float S [N_][N_];      // [49][49]

    int base_col = head * HD_;

    // Load q/k/v head slices (49 tokens x 32 dims), k and v transposed
    for (int idx = tid; idx < N_ * 8; idx += 128) {
        int n = idx >> 3, f = (idx & 7) * 4;
        int ir = n / 7, ic = n - (n / 7) * 7;
        size_t row = (size_t)(b * 56 + wr * 7 + ir) * 56 + (wc * 7 + ic);
        size_t off = row * C_ + base_col + f;
        float4 qv = *(const float4*)(q + off);
        *(float4*)&qs[n][f] = qv;
        float4 kv = *(const float4*)(k + off);
        kT[f + 0][n] = kv.x; kT[f + 1][n] = kv.y;
        kT[f + 2][n] = kv.z; kT[f + 3][n] = kv.w;
        float4 vv = *(const float4*)(v + off);
        vT[f + 0][n] = vv.x; vT[f + 1][n] = vv.y;
        vT[f + 2][n] = vv.z; vT[f + 3][n] = vv.w;
    }
    __syncthreads();

    // Logits: S[i][j] = scale * q_i . k_j + rel_bias[head][i][j]
    const float* rb = rel_bias + head * (N_ * N_);
    for (int idx = tid; idx < N_ * N_; idx += 128) {
        int i = idx / N_, j = idx - i * N_;
        float s = 0.0f;
        #pragma unroll
        for (int d = 0; d < HD_; d++) s = fmaf(qs[i][d], kT[d][j], s);
        S[i][j] = s * SCALE_ + rb[idx];
    }
    __syncthreads();

    // Row softmax: each warp owns rows round-robin
    int warp = tid >> 5, lane = tid & 31;
    for (int i = warp; i < N_; i += 4) {
        float m = -1e30f;
        for (int j = lane; j < N_; j += 32) m = fmaxf(m, S[i][j]);
        #pragma unroll
        for (int o = 16; o; o >>= 1) m = fmaxf(m, __shfl_xor_sync(0xffffffffu, m, o));
        float sum = 0.0f;
        for (int j = lane; j < N_; j += 32) {
            float e = __expf(S[i][j] - m);
            S[i][j] = e;
            sum += e;
        }
        #pragma unroll
        for (int o = 16; o; o >>= 1) sum += __shfl_xor_sync(0xffffffffu, sum, o);
        float inv = 1.0f / sum;
        for (int j = lane; j < N_; j += 32) S[i][j] *= inv;
    }
    __syncthreads();

    // out[i][d] = sum_j S[i][j] * v[j][d]; write to spatial layout
    for (int idx = tid; idx < N_ * HD_; idx += 128) {
        int i = idx >> 5, d = idx & 31;
        float s = 0.0f;
        #pragma unroll
        for (int j = 0; j < N_; j++) s = fmaf(S[i][j], vT[d][j], s);
        int ir = i / 7, ic = i - (i / 7) * 7;
        size_t row = (size_t)(b * 56 + wr * 7 + ir) * 56 + (wc * 7 + ic);
        ao[row * C_ + base_col + d] = s;
    }
}

// ---------------------------------------------------------------------------
// Launch
// ---------------------------------------------------------------------------
extern "C" void kernel_launch(void* const* d_in, const int* in_sizes, int n_in,
                              void* d_out, int out_size)
{
    const float* x    = (const float*)d_in[0];
    const float* Wq   = (const float*)d_in[1];
    const float* bq   = (const float*)d_in[2];
    const float* Wk   = (const float*)d_in[3];
    const float* bk   = (const float*)d_in[4];
    const float* Wv   = (const float*)d_in[5];
    const float* bv   = (const float*)d_in[6];
    const float* Wp   = (const float*)d_in[7];
    const float* bp   = (const float*)d_in[8];
    const float* rel  = (const float*)d_in[9];
    const float* g1   = (const float*)d_in[10];
    const float* b1   = (const float*)d_in[11];
    const float* g2   = (const float*)d_in[12];
    const float* b2   = (const float*)d_in[13];
    const float* W1   = (const float*)d_in[14];
    const float* bfc1 = (const float*)d_in[15];
    const float* W2   = (const float*)d_in[16];
    const float* bfc2 = (const float*)d_in[17];
    float* out = (float*)d_out;

    float *h, *q, *k, *v, *ao, *x2, *hid;
    cudaGetSymbolAddress((void**)&h,   g_h);
    cudaGetSymbolAddress((void**)&q,   g_q);
    cudaGetSymbolAddress((void**)&k,   g_k);
    cudaGetSymbolAddress((void**)&v,   g_v);
    cudaGetSymbolAddress((void**)&ao,  g_ao);
    cudaGetSymbolAddress((void**)&x2,  g_x2);
    cudaGetSymbolAddress((void**)&hid, g_hid);

    // 1. LN1
    ln_kernel<<<ROWS_, 128>>>(x, g1, b1, h);

    // 2. QKV projections
    dim3 gemm_grid_c(C_ / BN, ROWS_ / BM);
    gemm_kernel<<<gemm_grid_c, 256>>>(h, Wq, bq, nullptr, q, ROWS_, C_, C_, 0);
    gemm_kernel<<<gemm_grid_c, 256>>>(h, Wk, bk, nullptr, k, ROWS_, C_, C_, 0);
    gemm_kernel<<<gemm_grid_c, 256>>>(h, Wv, bv, nullptr, v, ROWS_, C_, C_, 0);

    // 3. Windowed attention (writes spatial layout)
    attn_kernel<<<dim3(B_ * NW_, NH_), 128>>>(q, k, v, rel, ao);

    // 4. Output projection + residual: x2 = x + ao @ Wp + bp
    gemm_kernel<<<gemm_grid_c, 256>>>(ao, Wp, bp, x, x2, ROWS_, C_, C_, 0);

    // 5. LN2
    ln_kernel<<<ROWS_, 128>>>(x2, g2, b2, h);

    // 6. MLP fc1 + exact GELU
    dim3 gemm_grid_h(HID_ / BN, ROWS_ / BM);
    gemm_kernel<<<gemm_grid_h, 256>>>(h, W1, bfc1, nullptr, hid, ROWS_, HID_, C_, 1);

    // 7. MLP fc2 + residual -> out
    gemm_kernel<<<gemm_grid_c, 256>>>(hid, W2, bfc2, x2, out, ROWS_, C_, HID_, 0);
}

// round 4
// speedup vs baseline: 2.2785x; 2.2785x over previous
#include <cuda_runtime.h>
#include <math.h>

typedef unsigned int u32;

// Problem constants
#define B_   16
#define H_   56
#define W_   56
#define C_   512
#define WS_  7
#define NH_  16
#define HD_  32
#define HID_ 2048
#define N_   49
#define NW_  64
#define L_   (H_ * W_)          // 3136
#define ROWS_ (B_ * L_)         // 50176
#define QKVC_ 1536
#define SCALE_ 0.17677669529663687f
#define EPS_ 1e-5f

// Scratch (device globals: allocation-free)
__device__ float g_h  [ROWS_ * C_];
__device__ float g_qkv[ROWS_ * QKVC_];
__device__ float g_ao [ROWS_ * C_];
__device__ float g_x2 [ROWS_ * C_];
__device__ float g_hid[ROWS_ * HID_];
__device__ float g_wtqkv[QKVC_ * C_];   // [1536][512]  (Wq^T | Wk^T | Wv^T)
__device__ float g_wtp  [C_ * C_];      // [512][512]
__device__ float g_wt1  [HID_ * C_];    // [2048][512]
__device__ float g_wt2  [C_ * HID_];    // [512][2048]
__device__ float g_bqkv [QKVC_];

// ---------------------------------------------------------------------------
// Helpers
// ---------------------------------------------------------------------------
__device__ __forceinline__ u32 f2tf(float f) {
    u32 r;
    asm("cvt.rna.tf32.f32 %0, %1;" : "=r"(r) : "f"(f));
    return r;
}
__device__ __forceinline__ void cp_async16(u32 saddr, const void* gptr) {
    asm volatile("cp.async.cg.shared.global [%0], [%1], 16;" :: "r"(saddr), "l"(gptr));
}
#define CP_COMMIT() asm volatile("cp.async.commit_group;")
#define CP_WAIT(n)  asm volatile("cp.async.wait_group %0;" :: "n"(n))

#define MMA_TF32(ac, ar, br)                                                    \
    asm volatile(                                                               \
        "mma.sync.aligned.m16n8k8.row.col.f32.tf32.tf32.f32 "                   \
        "{%0,%1,%2,%3},{%4,%5,%6,%7},{%8,%9},{%0,%1,%2,%3};"                    \
        : "+f"(ac[0]), "+f"(ac[1]), "+f"(ac[2]), "+f"(ac[3])                    \
        : "r"(ar[0]), "r"(ar[1]), "r"(ar[2]), "r"(ar[3]), "r"(br[0]), "r"(br[1]))

// ---------------------------------------------------------------------------
// Transpose: dst[Cc][R] = src[R][Cc]^T   (R, Cc multiples of 32)
// ---------------------------------------------------------------------------
__global__ __launch_bounds__(256) void transpose_kernel(
    const float* __restrict__ src, float* __restrict__ dst, int R, int Cc)
{
    __shared__ float tile[32][33];
    int bx = blockIdx.x * 32, by = blockIdx.y * 32;
    int tx = threadIdx.x, ty = threadIdx.y;   // 32 x 8
    #pragma unroll
    for (int i = 0; i < 32; i += 8)
        tile[ty + i][tx] = src[(size_t)(by + ty + i) * Cc + bx + tx];
    __syncthreads();
    #pragma unroll
    for (int i = 0; i < 32; i += 8)
        dst[(size_t)(bx + ty + i) * R + by + tx] = tile[tx][ty + i];
}

__global__ void pack_bias_kernel(const float* __restrict__ bq,
                                 const float* __restrict__ bk,
                                 const float* __restrict__ bv,
                                 float* __restrict__ dst)
{
    int i = blockIdx.x * 256 + threadIdx.x;
    if (i < QKVC_)
        dst[i] = i < 512 ? bq[i] : (i < 1024 ? bk[i - 512] : bv[i - 1024]);
}

// ---------------------------------------------------------------------------
// LayerNorm: one block per row of 512, 128 threads x float4
// ---------------------------------------------------------------------------
__global__ __launch_bounds__(128) void ln_kernel(const float* __restrict__ x,
                                                 const float* __restrict__ g,
                                                 const float* __restrict__ b,
                                                 float* __restrict__ out) {
    int row = blockIdx.x;
    const float4* xr = (const float4*)(x + (size_t)row * C_);
    float4 v = xr[threadIdx.x];
    float s  = v.x + v.y + v.z + v.w;
    float s2 = v.x * v.x + v.y * v.y + v.z * v.z + v.w * v.w;
    #pragma unroll
    for (int o = 16; o; o >>= 1) {
        s  += __shfl_xor_sync(0xffffffffu, s, o);
        s2 += __shfl_xor_sync(0xffffffffu, s2, o);
    }
    __shared__ float sm[4], sm2[4];
    int warp = threadIdx.x >> 5;
    if ((threadIdx.x & 31) == 0) { sm[warp] = s; sm2[warp] = s2; }
    __syncthreads();
    s  = sm[0] + sm[1] + sm[2] + sm[3];
    s2 = sm2[0] + sm2[1] + sm2[2] + sm2[3];
    float mu   = s * (1.0f / C_);
    float var  = s2 * (1.0f / C_) - mu * mu;
    float rstd = rsqrtf(var + EPS_);
    float4 gg = ((const float4*)g)[threadIdx.x];
    float4 bb = ((const float4*)b)[threadIdx.x];
    float4 o;
    o.x = (v.x - mu) * rstd * gg.x + bb.x;
    o.y = (v.y - mu) * rstd * gg.y + bb.y;
    o.z = (v.z - mu) * rstd * gg.z + bb.z;
    o.w = (v.w - mu) * rstd * gg.w + bb.w;
    ((float4*)(out + (size_t)row * C_))[threadIdx.x] = o;
}

// ---------------------------------------------------------------------------
// TF32 tensor-core GEMM: C[M,Nc] = A[M,K] @ Bt[Nc,K]^T + bias (+res)(+gelu)
// BM=BN=128, BK=16, 256 threads (8 warps, 2x4), warp tile 64x32 via m16n8k8.
// cp.async double-buffered smem.
// ---------------------------------------------------------------------------
#define GBM 128
#define GBN 128
#define GBK 16
#define GST 20

__global__ __launch_bounds__(256, 2) void mma_gemm(
    const float* __restrict__ A, const float* __restrict__ Bt,
    const float* __restrict__ bias, const float* __restrict__ res,
    float* __restrict__ C, int M, int Nc, int K, int do_gelu)
{
    __shared__ __align__(16) float shA[2][GBM * GST];
    __shared__ __align__(16) float shB[2][GBN * GST];

    const int tid = threadIdx.x;
    const int bm = blockIdx.y * GBM;
    const int bn = blockIdx.x * GBN;
    const int warp = tid >> 5, lane = tid & 31;
    const int wr = warp >> 2, wc = warp & 3;        // 2 x 4 warp grid
    const int grp = lane >> 2, tig = lane & 3;

    // load mapping: thread -> (row, 4-float k chunk); second row = +64
    const int lr = tid >> 2;
    const int lk = (tid & 3) << 2;

    const float* Ag0 = A  + (size_t)(bm + lr)      * K + lk;
    const float* Ag1 = A  + (size_t)(bm + lr + 64) * K + lk;
    const float* Bg0 = Bt + (size_t)(bn + lr)      * K + lk;
    const float* Bg1 = Bt + (size_t)(bn + lr + 64) * K + lk;

    u32 sA0 = (u32)__cvta_generic_to_shared(&shA[0][lr * GST + lk]);
    u32 sA1 = (u32)__cvta_generic_to_shared(&shA[1][lr * GST + lk]);
    u32 sB0 = (u32)__cvta_generic_to_shared(&shB[0][lr * GST + lk]);
    u32 sB1 = (u32)__cvta_generic_to_shared(&shB[1][lr * GST + lk]);
    const u32 roff = 64 * GST * 4;   // +64 rows in bytes

    float acc[4][4][4];
    #pragma unroll
    for (int mt = 0; mt < 4; mt++)
        #pragma unroll
        for (int nt = 0; nt < 4; nt++)
            #pragma unroll
            for (int r = 0; r < 4; r++) acc[mt][nt][r] = 0.0f;

    // prologue: stage 0
    cp_async16(sA0, Ag0); cp_async16(sA0 + roff, Ag1);
    cp_async16(sB0, Bg0); cp_async16(sB0 + roff, Bg1);
    CP_COMMIT();

    const int NT = K / GBK;
    for (int t = 0; t < NT; t++) {
        if (t + 1 < NT) {
            int k0 = (t + 1) * GBK;
            u32 sa = ((t + 1) & 1) ? sA1 : sA0;
            u32 sb = ((t + 1) & 1) ? sB1 : sB0;
            cp_async16(sa, Ag0 + k0); cp_async16(sa + roff, Ag1 + k0);
            cp_async16(sb, Bg0 + k0); cp_async16(sb + roff, Bg1 + k0);
            CP_COMMIT();
            CP_WAIT(1);
        } else {
            CP_WAIT(0);
        }
        __syncthreads();

        const float* smA = shA[t & 1];
        const float* smB = shB[t & 1];
        #pragma unroll
        for (int kk = 0; kk < GBK; kk += 8) {
            u32 fragA[4][4];
            u32 fragB[4][2];
            #pragma unroll
            for (int mt = 0; mt < 4; mt++) {
                int mb = wr * 64 + mt * 16;
                fragA[mt][0] = f2tf(smA[(mb + grp)     * GST + kk + tig]);
                fragA[mt][1] = f2tf(smA[(mb + grp + 8) * GST + kk + tig]);
                fragA[mt][2] = f2tf(smA[(mb + grp)     * GST + kk + tig + 4]);
                fragA[mt][3] = f2tf(smA[(mb + grp + 8) * GST + kk + tig + 4]);
            }
            #pragma unroll
            for (int nt = 0; nt < 4; nt++) {
                int nb = wc * 32 + nt * 8;
                fragB[nt][0] = f2tf(smB[(nb + grp) * GST + kk + tig]);
                fragB[nt][1] = f2tf(smB[(nb + grp) * GST + kk + tig + 4]);
            }
            #pragma unroll
            for (int mt = 0; mt < 4; mt++)
                #pragma unroll
                for (int nt = 0; nt < 4; nt++)
                    MMA_TF32(acc[mt][nt], fragA[mt], fragB[nt]);
        }
        __syncthreads();
    }

    // epilogue
    #pragma unroll
    for (int mt = 0; mt < 4; mt++) {
        #pragma unroll
        for (int i = 0; i < 2; i++) {
            int row = bm + wr * 64 + mt * 16 + grp + i * 8;
            #pragma unroll
            for (int nt = 0; nt < 4; nt++) {
                int col = bn + wc * 32 + nt * 8 + 2 * tig;
                float v0 = acc[mt][nt][2 * i + 0] + bias[col];
                float v1 = acc[mt][nt][2 * i + 1] + bias[col + 1];
                if (res) {
                    const float* rp = res + (size_t)row * Nc + col;
                    v0 += rp[0]; v1 += rp[1];
                }
                if (do_gelu) {
                    v0 = v0 * normcdff(v0);
                    v1 = v1 * normcdff(v1);
                }
                *(float2*)(C + (size_t)row * Nc + col) = make_float2(v0, v1);
            }
        }
    }
}

// ---------------------------------------------------------------------------
// Fused window attention: one block per (window, head), 128 threads.
// Reads q/k/v from packed qkv [ROWS][1536]; writes spatial (B,L,C) layout.
// ---------------------------------------------------------------------------
__global__ __launch_bounds__(128) void attn_kernel(
    const float* __restrict__ qkv, const float* __restrict__ rel_bias,
    float* __restrict__ ao)
{
    int w = blockIdx.x;          // 0..1023
    int head = blockIdx.y;       // 0..15
    int b  = w >> 6;
    int wi = w & 63;
    int wr = wi >> 3;
    int wc = wi & 7;
    int tid = threadIdx.x;

    __shared__ float qs[N_][HD_];
    __shared__ float kT[HD_][N_];
    __shared__ float vT[HD_][N_];
    __shared__ float S [N_][N_];

    int base_col = head * HD_;

    for (int idx = tid; idx < N_ * 8; idx += 128) {
        int n = idx >> 3, f = (idx & 7) * 4;
        int ir = n / 7, ic = n - (n / 7) * 7;
        size_t row = (size_t)(b * 56 + wr * 7 + ir) * 56 + (wc * 7 + ic);
        size_t off = row * QKVC_ + base_col + f;
        float4 qv = *(const float4*)(qkv + off);
        *(float4*)&qs[n][f] = qv;
        float4 kv = *(const float4*)(qkv + off + 512);
        kT[f + 0][n] = kv.x; kT[f + 1][n] = kv.y;
        kT[f + 2][n] = kv.z; kT[f + 3][n] = kv.w;
        float4 vv = *(const float4*)(qkv + off + 1024);
        vT[f + 0][n] = vv.x; vT[f + 1][n] = vv.y;
        vT[f + 2][n] = vv.z; vT[f + 3][n] = vv.w;
    }
    __syncthreads();

    const float* rb = rel_bias + head * (N_ * N_);
    for (int idx = tid; idx < N_ * N_; idx += 128) {
        int i = idx / N_, j = idx - i * N_;
        float s = 0.0f;
        #pragma unroll
        for (int d = 0; d < HD_; d++) s = fmaf(qs[i][d], kT[d][j], s);
        S[i][j] = s * SCALE_ + rb[idx];
    }
    __syncthreads();

    int warp = tid >> 5, lane = tid & 31;
    for (int i = warp; i < N_; i += 4) {
        float m = -1e30f;
        for (int j = lane; j < N_; j += 32) m = fmaxf(m, S[i][j]);
        #pragma unroll
        for (int o = 16; o; o >>= 1) m = fmaxf(m, __shfl_xor_sync(0xffffffffu, m, o));
        float sum = 0.0f;
        for (int j = lane; j < N_; j += 32) {
            float e = __expf(S[i][j] - m);
            S[i][j] = e;
            sum += e;
        }
        #pragma unroll
        for (int o = 16; o; o >>= 1) sum += __shfl_xor_sync(0xffffffffu, sum, o);
        float inv = 1.0f / sum;
        for (int j = lane; j < N_; j += 32) S[i][j] *= inv;
    }
    __syncthreads();

    for (int idx = tid; idx < N_ * HD_; idx += 128) {
        int i = idx >> 5, d = idx & 31;
        float s = 0.0f;
        #pragma unroll
        for (int j = 0; j < N_; j++) s = fmaf(S[i][j], vT[d][j], s);
        int ir = i / 7, ic = i - (i / 7) * 7;
        size_t row = (size_t)(b * 56 + wr * 7 + ir) * 56 + (wc * 7 + ic);
        ao[row * C_ + base_col + d] = s;
    }
}

// ---------------------------------------------------------------------------
// Launch
// ---------------------------------------------------------------------------
extern "C" void kernel_launch(void* const* d_in, const int* in_sizes, int n_in,
                              void* d_out, int out_size)
{
    const float* x    = (const float*)d_in[0];
    const float* Wq   = (const float*)d_in[1];
    const float* bq   = (const float*)d_in[2];
    const float* Wk   = (const float*)d_in[3];
    const float* bk   = (const float*)d_in[4];
    const float* Wv   = (const float*)d_in[5];
    const float* bv   = (const float*)d_in[6];
    const float* Wp   = (const float*)d_in[7];
    const float* bp   = (const float*)d_in[8];
    const float* rel  = (const float*)d_in[9];
    const float* g1   = (const float*)d_in[10];
    const float* b1   = (const float*)d_in[11];
    const float* g2   = (const float*)d_in[12];
    const float* b2   = (const float*)d_in[13];
    const float* W1   = (const float*)d_in[14];
    const float* bfc1 = (const float*)d_in[15];
    const float* W2   = (const float*)d_in[16];
    const float* bfc2 = (const float*)d_in[17];
    float* out = (float*)d_out;

    float *h, *qkv, *ao, *x2, *hid, *wtqkv, *wtp, *wt1, *wt2, *bqkv;
    cudaGetSymbolAddress((void**)&h,     g_h);
    cudaGetSymbolAddress((void**)&qkv,   g_qkv);
    cudaGetSymbolAddress((void**)&ao,    g_ao);
    cudaGetSymbolAddress((void**)&x2,    g_x2);
    cudaGetSymbolAddress((void**)&hid,   g_hid);
    cudaGetSymbolAddress((void**)&wtqkv, g_wtqkv);
    cudaGetSymbolAddress((void**)&wtp,   g_wtp);
    cudaGetSymbolAddress((void**)&wt1,   g_wt1);
    cudaGetSymbolAddress((void**)&wt2,   g_wt2);
    cudaGetSymbolAddress((void**)&bqkv,  g_bqkv);

    // 0. Weight transposes (K-major) + bias packing
    dim3 tb(32, 8);
    transpose_kernel<<<dim3(C_ / 32, C_ / 32), tb>>>(Wq, wtqkv,             C_, C_);
    transpose_kernel<<<dim3(C_ / 32, C_ / 32), tb>>>(Wk, wtqkv + 512 * C_,  C_, C_);
    transpose_kernel<<<dim3(C_ / 32, C_ / 32), tb>>>(Wv, wtqkv + 1024 * C_, C_, C_);
    transpose_kernel<<<dim3(C_ / 32, C_ / 32), tb>>>(Wp, wtp, C_, C_);
    transpose_kernel<<<dim3(HID_ / 32, C_ / 32), tb>>>(W1, wt1, C_, HID_);
    transpose_kernel<<<dim3(C_ / 32, HID_ / 32), tb>>>(W2, wt2, HID_, C_);
    pack_bias_kernel<<<6, 256>>>(bq, bk, bv, bqkv);

    // 1. LN1
    ln_kernel<<<ROWS_, 128>>>(x, g1, b1, h);

    // 2. Fused QKV projection (N = 1536)
    mma_gemm<<<dim3(QKVC_ / GBN, ROWS_ / GBM), 256>>>(
        h, wtqkv, bqkv, nullptr, qkv, ROWS_, QKVC_, C_, 0);

    // 3. Windowed attention
    attn_kernel<<<dim3(B_ * NW_, NH_), 128>>>(qkv, rel, ao);

    // 4. Output projection + residual: x2 = x + ao @ Wp + bp
    mma_gemm<<<dim3(C_ / GBN, ROWS_ / GBM), 256>>>(
        ao, wtp, bp, x, x2, ROWS_, C_, C_, 0);

    // 5. LN2
    ln_kernel<<<ROWS_, 128>>>(x2, g2, b2, h);

    // 6. MLP fc1 + exact GELU
    mma_gemm<<<dim3(HID_ / GBN, ROWS_ / GBM), 256>>>(
        h, wt1, bfc1, nullptr, hid, ROWS_, HID_, C_, 1);

    // 7. MLP fc2 + residual -> out
    mma_gemm<<<dim3(C_ / GBN, ROWS_ / GBM), 256>>>(
        hid, wt2, bfc2, x2, out, ROWS_, C_, HID_, 0);
}

// round 5
// speedup vs baseline: 2.2891x; 1.0046x over previous
#include <cuda_runtime.h>
#include <math.h>

typedef unsigned int u32;

// Problem constants
#define B_   16
#define H_   56
#define W_   56
#define C_   512
#define WS_  7
#define NH_  16
#define HD_  32
#define HID_ 2048
#define N_   49
#define NW_  64
#define L_   (H_ * W_)          // 3136
#define ROWS_ (B_ * L_)         // 50176
#define QKVC_ 1536
#define SCALE_ 0.17677669529663687f
#define EPS_ 1e-5f

// Scratch (device globals: allocation-free)
__device__ float g_h  [ROWS_ * C_];
__device__ float g_qkv[ROWS_ * QKVC_];
__device__ float g_ao [ROWS_ * C_];
__device__ float g_x2 [ROWS_ * C_];
__device__ float g_hid[ROWS_ * HID_];
__device__ float g_wtqkv[QKVC_ * C_];   // [1536][512]  (Wq^T | Wk^T | Wv^T), tf32-rounded
__device__ float g_wtp  [C_ * C_];      // tf32-rounded
__device__ float g_wt1  [HID_ * C_];    // tf32-rounded
__device__ float g_wt2  [C_ * HID_];    // tf32-rounded
__device__ float g_bqkv [QKVC_];

// ---------------------------------------------------------------------------
// Helpers
// ---------------------------------------------------------------------------
__device__ __forceinline__ u32 f2tf(float f) {
    u32 r;
    asm("cvt.rna.tf32.f32 %0, %1;" : "=r"(r) : "f"(f));
    return r;
}
__device__ __forceinline__ float f2tf_f(float f) {
    u32 r = f2tf(f);
    return __uint_as_float(r);
}
__device__ __forceinline__ void cp_async16(u32 saddr, const void* gptr) {
    asm volatile("cp.async.cg.shared.global [%0], [%1], 16;" :: "r"(saddr), "l"(gptr));
}
#define CP_COMMIT() asm volatile("cp.async.commit_group;")
#define CP_WAIT(n)  asm volatile("cp.async.wait_group %0;" :: "n"(n))

#define MMA_TF32(ac, ar, br)                                                    \
    asm volatile(                                                               \
        "mma.sync.aligned.m16n8k8.row.col.f32.tf32.tf32.f32 "                   \
        "{%0,%1,%2,%3},{%4,%5,%6,%7},{%8,%9},{%0,%1,%2,%3};"                    \
        : "+f"(ac[0]), "+f"(ac[1]), "+f"(ac[2]), "+f"(ac[3])                    \
        : "r"(ar[0]), "r"(ar[1]), "r"(ar[2]), "r"(ar[3]), "r"(br[0]), "r"(br[1]))

// ---------------------------------------------------------------------------
// Transpose + tf32 round: dst[Cc][R] = tf32(src[R][Cc]^T)
// ---------------------------------------------------------------------------
__global__ __launch_bounds__(256) void transpose_kernel(
    const float* __restrict__ src, float* __restrict__ dst, int R, int Cc)
{
    __shared__ float tile[32][33];
    int bx = blockIdx.x * 32, by = blockIdx.y * 32;
    int tx = threadIdx.x, ty = threadIdx.y;   // 32 x 8
    #pragma unroll
    for (int i = 0; i < 32; i += 8)
        tile[ty + i][tx] = src[(size_t)(by + ty + i) * Cc + bx + tx];
    __syncthreads();
    #pragma unroll
    for (int i = 0; i < 32; i += 8)
        dst[(size_t)(bx + ty + i) * R + by + tx] = f2tf_f(tile[tx][ty + i]);
}

__global__ void pack_bias_kernel(const float* __restrict__ bq,
                                 const float* __restrict__ bk,
                                 const float* __restrict__ bv,
                                 float* __restrict__ dst)
{
    int i = blockIdx.x * 256 + threadIdx.x;
    if (i < QKVC_)
        dst[i] = i < 512 ? bq[i] : (i < 1024 ? bk[i - 512] : bv[i - 1024]);
}

// ---------------------------------------------------------------------------
// LayerNorm (output tf32-rounded; consumed only by GEMMs)
// ---------------------------------------------------------------------------
__global__ __launch_bounds__(128) void ln_kernel(const float* __restrict__ x,
                                                 const float* __restrict__ g,
                                                 const float* __restrict__ b,
                                                 float* __restrict__ out) {
    int row = blockIdx.x;
    const float4* xr = (const float4*)(x + (size_t)row * C_);
    float4 v = xr[threadIdx.x];
    float s  = v.x + v.y + v.z + v.w;
    float s2 = v.x * v.x + v.y * v.y + v.z * v.z + v.w * v.w;
    #pragma unroll
    for (int o = 16; o; o >>= 1) {
        s  += __shfl_xor_sync(0xffffffffu, s, o);
        s2 += __shfl_xor_sync(0xffffffffu, s2, o);
    }
    __shared__ float sm[4], sm2[4];
    int warp = threadIdx.x >> 5;
    if ((threadIdx.x & 31) == 0) { sm[warp] = s; sm2[warp] = s2; }
    __syncthreads();
    s  = sm[0] + sm[1] + sm[2] + sm[3];
    s2 = sm2[0] + sm2[1] + sm2[2] + sm2[3];
    float mu   = s * (1.0f / C_);
    float var  = s2 * (1.0f / C_) - mu * mu;
    float rstd = rsqrtf(var + EPS_);
    float4 gg = ((const float4*)g)[threadIdx.x];
    float4 bb = ((const float4*)b)[threadIdx.x];
    float4 o;
    o.x = f2tf_f((v.x - mu) * rstd * gg.x + bb.x);
    o.y = f2tf_f((v.y - mu) * rstd * gg.y + bb.y);
    o.z = f2tf_f((v.z - mu) * rstd * gg.z + bb.z);
    o.w = f2tf_f((v.w - mu) * rstd * gg.w + bb.w);
    ((float4*)(out + (size_t)row * C_))[threadIdx.x] = o;
}

// ---------------------------------------------------------------------------
// TF32 tensor-core GEMM: C[M,Nc] = A[M,K] @ Bt[Nc,K]^T + bias (+res)(+gelu)
// Inputs pre-rounded to tf32 -> raw-bit fragments, no in-loop cvt.
// BM=BN=128, BK=16, 256 threads (8 warps, 2x4), warp tile 64x32 via m16n8k8.
// Single __syncthreads per k-tile.
// ---------------------------------------------------------------------------
#define GBM 128
#define GBN 128
#define GBK 16
#define GST 20

__global__ __launch_bounds__(256, 2) void mma_gemm(
    const float* __restrict__ A, const float* __restrict__ Bt,
    const float* __restrict__ bias, const float* __restrict__ res,
    float* __restrict__ C, int M, int Nc, int K, int do_gelu)
{
    __shared__ __align__(16) float shA[2][GBM * GST];
    __shared__ __align__(16) float shB[2][GBN * GST];

    const int tid = threadIdx.x;
    const int bm = blockIdx.y * GBM;
    const int bn = blockIdx.x * GBN;
    const int warp = tid >> 5, lane = tid & 31;
    const int wr = warp >> 2, wc = warp & 3;        // 2 x 4 warp grid
    const int grp = lane >> 2, tig = lane & 3;

    const int lr = tid >> 2;
    const int lk = (tid & 3) << 2;

    const float* Ag0 = A  + (size_t)(bm + lr)      * K + lk;
    const float* Ag1 = A  + (size_t)(bm + lr + 64) * K + lk;
    const float* Bg0 = Bt + (size_t)(bn + lr)      * K + lk;
    const float* Bg1 = Bt + (size_t)(bn + lr + 64) * K + lk;

    u32 sA0 = (u32)__cvta_generic_to_shared(&shA[0][lr * GST + lk]);
    u32 sA1 = (u32)__cvta_generic_to_shared(&shA[1][lr * GST + lk]);
    u32 sB0 = (u32)__cvta_generic_to_shared(&shB[0][lr * GST + lk]);
    u32 sB1 = (u32)__cvta_generic_to_shared(&shB[1][lr * GST + lk]);
    const u32 roff = 64 * GST * 4;   // +64 rows in bytes

    float acc[4][4][4];
    #pragma unroll
    for (int mt = 0; mt < 4; mt++)
        #pragma unroll
        for (int nt = 0; nt < 4; nt++)
            #pragma unroll
            for (int r = 0; r < 4; r++) acc[mt][nt][r] = 0.0f;

    // prologue: stage 0
    cp_async16(sA0, Ag0); cp_async16(sA0 + roff, Ag1);
    cp_async16(sB0, Bg0); cp_async16(sB0 + roff, Bg1);
    CP_COMMIT();

    const int NT = K / GBK;
    for (int t = 0; t < NT; t++) {
        CP_WAIT(0);
        __syncthreads();

        if (t + 1 < NT) {
            int k0 = (t + 1) * GBK;
            u32 sa = ((t + 1) & 1) ? sA1 : sA0;
            u32 sb = ((t + 1) & 1) ? sB1 : sB0;
            cp_async16(sa, Ag0 + k0); cp_async16(sa + roff, Ag1 + k0);
            cp_async16(sb, Bg0 + k0); cp_async16(sb + roff, Bg1 + k0);
            CP_COMMIT();
        }

        const u32* smA = (const u32*)shA[t & 1];
        const u32* smB = (const u32*)shB[t & 1];
        #pragma unroll
        for (int kk = 0; kk < GBK; kk += 8) {
            u32 fragA[4][4];
            u32 fragB[4][2];
            #pragma unroll
            for (int mt = 0; mt < 4; mt++) {
                int mb = wr * 64 + mt * 16;
                fragA[mt][0] = smA[(mb + grp)     * GST + kk + tig];
                fragA[mt][1] = smA[(mb + grp + 8) * GST + kk + tig];
                fragA[mt][2] = smA[(mb + grp)     * GST + kk + tig + 4];
                fragA[mt][3] = smA[(mb + grp + 8) * GST + kk + tig + 4];
            }
            #pragma unroll
            for (int nt = 0; nt < 4; nt++) {
                int nb = wc * 32 + nt * 8;
                fragB[nt][0] = smB[(nb + grp) * GST + kk + tig];
                fragB[nt][1] = smB[(nb + grp) * GST + kk + tig + 4];
            }
            #pragma unroll
            for (int mt = 0; mt < 4; mt++)
                #pragma unroll
                for (int nt = 0; nt < 4; nt++)
                    MMA_TF32(acc[mt][nt], fragA[mt], fragB[nt]);
        }
    }

    // epilogue  (do_gelu also tf32-rounds the output: it feeds the fc2 GEMM)
    #pragma unroll
    for (int mt = 0; mt < 4; mt++) {
        #pragma unroll
        for (int i = 0; i < 2; i++) {
            int row = bm + wr * 64 + mt * 16 + grp + i * 8;
            #pragma unroll
            for (int nt = 0; nt < 4; nt++) {
                int col = bn + wc * 32 + nt * 8 + 2 * tig;
                float v0 = acc[mt][nt][2 * i + 0] + bias[col];
                float v1 = acc[mt][nt][2 * i + 1] + bias[col + 1];
                if (res) {
                    const float* rp = res + (size_t)row * Nc + col;
                    v0 += rp[0]; v1 += rp[1];
                }
                if (do_gelu) {
                    v0 = f2tf_f(v0 * normcdff(v0));
                    v1 = f2tf_f(v1 * normcdff(v1));
                }
                *(float2*)(C + (size_t)row * Nc + col) = make_float2(v0, v1);
            }
        }
    }
}

// ---------------------------------------------------------------------------
// Fused window attention (output tf32-rounded; consumed by proj GEMM)
// ---------------------------------------------------------------------------
__global__ __launch_bounds__(128) void attn_kernel(
    const float* __restrict__ qkv, const float* __restrict__ rel_bias,
    float* __restrict__ ao)
{
    int w = blockIdx.x;          // 0..1023
    int head = blockIdx.y;       // 0..15
    int b  = w >> 6;
    int wi = w & 63;
    int wr = wi >> 3;
    int wc = wi & 7;
    int tid = threadIdx.x;

    __shared__ float qs[N_][HD_];
    __shared__ float kT[HD_][N_];
    __shared__ float vT[HD_][N_];
    __shared__ float S [N_][N_];

    int base_col = head * HD_;

    for (int idx = tid; idx < N_ * 8; idx += 128) {
        int n = idx >> 3, f = (idx & 7) * 4;
        int ir = n / 7, ic = n - (n / 7) * 7;
        size_t row = (size_t)(b * 56 + wr * 7 + ir) * 56 + (wc * 7 + ic);
        size_t off = row * QKVC_ + base_col + f;
        float4 qv = *(const float4*)(qkv + off);
        *(float4*)&qs[n][f] = qv;
        float4 kv = *(const float4*)(qkv + off + 512);
        kT[f + 0][n] = kv.x; kT[f + 1][n] = kv.y;
        kT[f + 2][n] = kv.z; kT[f + 3][n] = kv.w;
        float4 vv = *(const float4*)(qkv + off + 1024);
        vT[f + 0][n] = vv.x; vT[f + 1][n] = vv.y;
        vT[f + 2][n] = vv.z; vT[f + 3][n] = vv.w;
    }
    __syncthreads();

    const float* rb = rel_bias + head * (N_ * N_);
    for (int idx = tid; idx < N_ * N_; idx += 128) {
        int i = idx / N_, j = idx - i * N_;
        float s = 0.0f;
        #pragma unroll
        for (int d = 0; d < HD_; d++) s = fmaf(qs[i][d], kT[d][j], s);
        S[i][j] = s * SCALE_ + rb[idx];
    }
    __syncthreads();

    int warp = tid >> 5, lane = tid & 31;
    for (int i = warp; i < N_; i += 4) {
        float m = -1e30f;
        for (int j = lane; j < N_; j += 32) m = fmaxf(m, S[i][j]);
        #pragma unroll
        for (int o = 16; o; o >>= 1) m = fmaxf(m, __shfl_xor_sync(0xffffffffu, m, o));
        float sum = 0.0f;
        for (int j = lane; j < N_; j += 32) {
            float e = __expf(S[i][j] - m);
            S[i][j] = e;
            sum += e;
        }
        #pragma unroll
        for (int o = 16; o; o >>= 1) sum += __shfl_xor_sync(0xffffffffu, sum, o);
        float inv = 1.0f / sum;
        for (int j = lane; j < N_; j += 32) S[i][j] *= inv;
    }
    __syncthreads();

    for (int idx = tid; idx < N_ * HD_; idx += 128) {
        int i = idx >> 5, d = idx & 31;
        float s = 0.0f;
        #pragma unroll
        for (int j = 0; j < N_; j++) s = fmaf(S[i][j], vT[d][j], s);
        int ir = i / 7, ic = i - (i / 7) * 7;
        size_t row = (size_t)(b * 56 + wr * 7 + ir) * 56 + (wc * 7 + ic);
        ao[row * C_ + base_col + d] = f2tf_f(s);
    }
}

// ---------------------------------------------------------------------------
// Launch
// ---------------------------------------------------------------------------
extern "C" void kernel_launch(void* const* d_in, const int* in_sizes, int n_in,
                              void* d_out, int out_size)
{
    const float* x    = (const float*)d_in[0];
    const float* Wq   = (const float*)d_in[1];
    const float* bq   = (const float*)d_in[2];
    const float* Wk   = (const float*)d_in[3];
    const float* bk   = (const float*)d_in[4];
    const float* Wv   = (const float*)d_in[5];
    const float* bv   = (const float*)d_in[6];
    const float* Wp   = (const float*)d_in[7];
    const float* bp   = (const float*)d_in[8];
    const float* rel  = (const float*)d_in[9];
    const float* g1   = (const float*)d_in[10];
    const float* b1   = (const float*)d_in[11];
    const float* g2   = (const float*)d_in[12];
    const float* b2   = (const float*)d_in[13];
    const float* W1   = (const float*)d_in[14];
    const float* bfc1 = (const float*)d_in[15];
    const float* W2   = (const float*)d_in[16];
    const float* bfc2 = (const float*)d_in[17];
    float* out = (float*)d_out;

    float *h, *qkv, *ao, *x2, *hid, *wtqkv, *wtp, *wt1, *wt2, *bqkv;
    cudaGetSymbolAddress((void**)&h,     g_h);
    cudaGetSymbolAddress((void**)&qkv,   g_qkv);
    cudaGetSymbolAddress((void**)&ao,    g_ao);
    cudaGetSymbolAddress((void**)&x2,    g_x2);
    cudaGetSymbolAddress((void**)&hid,   g_hid);
    cudaGetSymbolAddress((void**)&wtqkv, g_wtqkv);
    cudaGetSymbolAddress((void**)&wtp,   g_wtp);
    cudaGetSymbolAddress((void**)&wt1,   g_wt1);
    cudaGetSymbolAddress((void**)&wt2,   g_wt2);
    cudaGetSymbolAddress((void**)&bqkv,  g_bqkv);

    // 0. Weight transposes (K-major, tf32-rounded) + bias packing
    dim3 tb(32, 8);
    transpose_kernel<<<dim3(C_ / 32, C_ / 32), tb>>>(Wq, wtqkv,             C_, C_);
    transpose_kernel<<<dim3(C_ / 32, C_ / 32), tb>>>(Wk, wtqkv + 512 * C_,  C_, C_);
    transpose_kernel<<<dim3(C_ / 32, C_ / 32), tb>>>(Wv, wtqkv + 1024 * C_, C_, C_);
    transpose_kernel<<<dim3(C_ / 32, C_ / 32), tb>>>(Wp, wtp, C_, C_);
    transpose_kernel<<<dim3(HID_ / 32, C_ / 32), tb>>>(W1, wt1, C_, HID_);
    transpose_kernel<<<dim3(C_ / 32, HID_ / 32), tb>>>(W2, wt2, HID_, C_);
    pack_bias_kernel<<<6, 256>>>(bq, bk, bv, bqkv);

    // 1. LN1
    ln_kernel<<<ROWS_, 128>>>(x, g1, b1, h);

    // 2. Fused QKV projection (N = 1536)
    mma_gemm<<<dim3(QKVC_ / GBN, ROWS_ / GBM), 256>>>(
        h, wtqkv, bqkv, nullptr, qkv, ROWS_, QKVC_, C_, 0);

    // 3. Windowed attention
    attn_kernel<<<dim3(B_ * NW_, NH_), 128>>>(qkv, rel, ao);

    // 4. Output projection + residual: x2 = x + ao @ Wp + bp
    mma_gemm<<<dim3(C_ / GBN, ROWS_ / GBM), 256>>>(
        ao, wtp, bp, x, x2, ROWS_, C_, C_, 0);

    // 5. LN2
    ln_kernel<<<ROWS_, 128>>>(x2, g2, b2, h);

    // 6. MLP fc1 + exact GELU (output tf32-rounded for fc2)
    mma_gemm<<<dim3(HID_ / GBN, ROWS_ / GBM), 256>>>(
        h, wt1, bfc1, nullptr, hid, ROWS_, HID_, C_, 1);

    // 7. MLP fc2 + residual -> out
    mma_gemm<<<dim3(C_ / GBN, ROWS_ / GBM), 256>>>(
        hid, wt2, bfc2, x2, out, ROWS_, C_, HID_, 0);
}

// round 6
// speedup vs baseline: 3.4978x; 1.5280x over previous
#include <cuda_runtime.h>
#include <cuda_fp16.h>
#include <math.h>

typedef unsigned int u32;

// Problem constants
#define B_   16
#define H_   56
#define W_   56
#define C_   512
#define WS_  7
#define NH_  16
#define HD_  32
#define HID_ 2048
#define N_   49
#define NW_  64
#define L_   (H_ * W_)          // 3136
#define ROWS_ (B_ * L_)         // 50176
#define QKVC_ 1536
#define SCALE_ 0.17677669529663687f
#define EPS_ 1e-5f

// Scratch (device globals: allocation-free)
__device__ __half g_h  [ROWS_ * C_];
__device__ float  g_qkv[ROWS_ * QKVC_];
__device__ __half g_ao [ROWS_ * C_];
__device__ float  g_x2 [ROWS_ * C_];
__device__ __half g_hid[ROWS_ * HID_];
__device__ __half g_wtqkv[QKVC_ * C_];   // [1536][512]  (Wq^T | Wk^T | Wv^T)
__device__ __half g_wtp  [C_ * C_];
__device__ __half g_wt1  [HID_ * C_];
__device__ __half g_wt2  [C_ * HID_];
__device__ float  g_bqkv [QKVC_];

// ---------------------------------------------------------------------------
// Helpers
// ---------------------------------------------------------------------------
__device__ __forceinline__ void cp_async16(u32 saddr, const void* gptr) {
    asm volatile("cp.async.cg.shared.global [%0], [%1], 16;" :: "r"(saddr), "l"(gptr));
}
#define CP_COMMIT() asm volatile("cp.async.commit_group;")
#define CP_WAIT(n)  asm volatile("cp.async.wait_group %0;" :: "n"(n))

#define MMA_F16(ac, ar, br)                                                     \
    asm volatile(                                                               \
        "mma.sync.aligned.m16n8k16.row.col.f32.f16.f16.f32 "                    \
        "{%0,%1,%2,%3},{%4,%5,%6,%7},{%8,%9},{%0,%1,%2,%3};"                    \
        : "+f"(ac[0]), "+f"(ac[1]), "+f"(ac[2]), "+f"(ac[3])                    \
        : "r"(ar[0]), "r"(ar[1]), "r"(ar[2]), "r"(ar[3]), "r"(br[0]), "r"(br[1]))

// ---------------------------------------------------------------------------
// Transpose + fp16 convert: dst[Cc][R] = half(src[R][Cc]^T)
// ---------------------------------------------------------------------------
__global__ __launch_bounds__(256) void transpose_kernel(
    const float* __restrict__ src, __half* __restrict__ dst, int R, int Cc)
{
    __shared__ float tile[32][33];
    int bx = blockIdx.x * 32, by = blockIdx.y * 32;
    int tx = threadIdx.x, ty = threadIdx.y;   // 32 x 8
    #pragma unroll
    for (int i = 0; i < 32; i += 8)
        tile[ty + i][tx] = src[(size_t)(by + ty + i) * Cc + bx + tx];
    __syncthreads();
    #pragma unroll
    for (int i = 0; i < 32; i += 8)
        dst[(size_t)(bx + ty + i) * R + by + tx] = __float2half_rn(tile[tx][ty + i]);
}

__global__ void pack_bias_kernel(const float* __restrict__ bq,
                                 const float* __restrict__ bk,
                                 const float* __restrict__ bv,
                                 float* __restrict__ dst)
{
    int i = blockIdx.x * 256 + threadIdx.x;
    if (i < QKVC_)
        dst[i] = i < 512 ? bq[i] : (i < 1024 ? bk[i - 512] : bv[i - 1024]);
}

// ---------------------------------------------------------------------------
// LayerNorm: fp32 in, fp16 out (consumed only by GEMMs)
// ---------------------------------------------------------------------------
__global__ __launch_bounds__(128) void ln_kernel(const float* __restrict__ x,
                                                 const float* __restrict__ g,
                                                 const float* __restrict__ b,
                                                 __half* __restrict__ out) {
    int row = blockIdx.x;
    const float4* xr = (const float4*)(x + (size_t)row * C_);
    float4 v = xr[threadIdx.x];
    float s  = v.x + v.y + v.z + v.w;
    float s2 = v.x * v.x + v.y * v.y + v.z * v.z + v.w * v.w;
    #pragma unroll
    for (int o = 16; o; o >>= 1) {
        s  += __shfl_xor_sync(0xffffffffu, s, o);
        s2 += __shfl_xor_sync(0xffffffffu, s2, o);
    }
    __shared__ float sm[4], sm2[4];
    int warp = threadIdx.x >> 5;
    if ((threadIdx.x & 31) == 0) { sm[warp] = s; sm2[warp] = s2; }
    __syncthreads();
    s  = sm[0] + sm[1] + sm[2] + sm[3];
    s2 = sm2[0] + sm2[1] + sm2[2] + sm2[3];
    float mu   = s * (1.0f / C_);
    float var  = s2 * (1.0f / C_) - mu * mu;
    float rstd = rsqrtf(var + EPS_);
    float4 gg = ((const float4*)g)[threadIdx.x];
    float4 bb = ((const float4*)b)[threadIdx.x];
    __half2 h0 = __floats2half2_rn((v.x - mu) * rstd * gg.x + bb.x,
                                   (v.y - mu) * rstd * gg.y + bb.y);
    __half2 h1 = __floats2half2_rn((v.z - mu) * rstd * gg.z + bb.z,
                                   (v.w - mu) * rstd * gg.w + bb.w);
    __half2* op = (__half2*)(out + (size_t)row * C_);
    op[threadIdx.x * 2 + 0] = h0;
    op[threadIdx.x * 2 + 1] = h1;
}

// ---------------------------------------------------------------------------
// FP16 tensor-core GEMM: C[M,Nc] = A[M,K] @ Bt[Nc,K]^T + bias (+res)(+gelu)
// BM=BN=128, BK=32, 256 threads (8 warps, 2x4), warp tile 64x32 via m16n8k16.
// Smem row: 16 data u32 + 4 pad (stride 20 u32) -> conflict-free fragments.
// Output to fp32 (Cf) or fp16 (Ch).
// ---------------------------------------------------------------------------
#define GBM 128
#define GBN 128
#define GBK 32
#define GSU 20          // u32 stride per row

__global__ __launch_bounds__(256, 2) void mma_gemm(
    const __half* __restrict__ A, const __half* __restrict__ Bt,
    const float* __restrict__ bias, const float* __restrict__ res,
    float* __restrict__ Cf, __half* __restrict__ Ch,
    int M, int Nc, int K, int do_gelu)
{
    __shared__ __align__(16) u32 shA[2][GBM * GSU];
    __shared__ __align__(16) u32 shB[2][GBN * GSU];

    const int tid = threadIdx.x;
    const int bm = blockIdx.y * GBM;
    const int bn = blockIdx.x * GBN;
    const int warp = tid >> 5, lane = tid & 31;
    const int wr = warp >> 2, wc = warp & 3;        // 2 x 4 warp grid
    const int grp = lane >> 2, tig = lane & 3;

    // chunk mapping: 512 16B-chunks per tile, 2 per thread (rows 0-63, 64-127)
    const int r0 = tid >> 2;            // 0..63
    const int kc = (tid & 3) * 8;       // half offset within row (8 halfs/chunk)

    const __half* Ag0 = A  + (size_t)(bm + r0)      * K + kc;
    const __half* Ag1 = A  + (size_t)(bm + r0 + 64) * K + kc;
    const __half* Bg0 = Bt + (size_t)(bn + r0)      * K + kc;
    const __half* Bg1 = Bt + (size_t)(bn + r0 + 64) * K + kc;

    u32 sA0 = (u32)__cvta_generic_to_shared(&shA[0][r0 * GSU + (tid & 3) * 4]);
    u32 sA1 = (u32)__cvta_generic_to_shared(&shA[1][r0 * GSU + (tid & 3) * 4]);
    u32 sB0 = (u32)__cvta_generic_to_shared(&shB[0][r0 * GSU + (tid & 3) * 4]);
    u32 sB1 = (u32)__cvta_generic_to_shared(&shB[1][r0 * GSU + (tid & 3) * 4]);
    const u32 roff = 64 * GSU * 4;   // +64 rows in bytes

    float acc[4][4][4];
    #pragma unroll
    for (int mt = 0; mt < 4; mt++)
        #pragma unroll
        for (int nt = 0; nt < 4; nt++)
            #pragma unroll
            for (int r = 0; r < 4; r++) acc[mt][nt][r] = 0.0f;

    // prologue: stage 0
    cp_async16(sA0, Ag0); cp_async16(sA0 + roff, Ag1);
    cp_async16(sB0, Bg0); cp_async16(sB0 + roff, Bg1);
    CP_COMMIT();

    const int NT = K / GBK;
    for (int t = 0; t < NT; t++) {
        CP_WAIT(0);
        __syncthreads();

        if (t + 1 < NT) {
            int k0 = (t + 1) * GBK;
            u32 sa = ((t + 1) & 1) ? sA1 : sA0;
            u32 sb = ((t + 1) & 1) ? sB1 : sB0;
            cp_async16(sa, Ag0 + k0); cp_async16(sa + roff, Ag1 + k0);
            cp_async16(sb, Bg0 + k0); cp_async16(sb + roff, Bg1 + k0);
            CP_COMMIT();
        }

        const u32* smA = shA[t & 1];
        const u32* smB = shB[t & 1];
        #pragma unroll
        for (int kk = 0; kk < 2; kk++) {           // two k16 steps
            const int ko = kk * 8;                 // u32 offset
            u32 fragA[4][4];
            u32 fragB[4][2];
            #pragma unroll
            for (int mt = 0; mt < 4; mt++) {
                int mb = wr * 64 + mt * 16;
                fragA[mt][0] = smA[(mb + grp)     * GSU + ko + tig];
                fragA[mt][1] = smA[(mb + grp + 8) * GSU + ko + tig];
                fragA[mt][2] = smA[(mb + grp)     * GSU + ko + tig + 4];
                fragA[mt][3] = smA[(mb + grp + 8) * GSU + ko + tig + 4];
            }
            #pragma unroll
            for (int nt = 0; nt < 4; nt++) {
                int nb = wc * 32 + nt * 8;
                fragB[nt][0] = smB[(nb + grp) * GSU + ko + tig];
                fragB[nt][1] = smB[(nb + grp) * GSU + ko + tig + 4];
            }
            #pragma unroll
            for (int mt = 0; mt < 4; mt++)
                #pragma unroll
                for (int nt = 0; nt < 4; nt++)
                    MMA_F16(acc[mt][nt], fragA[mt], fragB[nt]);
        }
    }

    // epilogue
    #pragma unroll
    for (int mt = 0; mt < 4; mt++) {
        #pragma unroll
        for (int i = 0; i < 2; i++) {
            int row = bm + wr * 64 + mt * 16 + grp + i * 8;
            #pragma unroll
            for (int nt = 0; nt < 4; nt++) {
                int col = bn + wc * 32 + nt * 8 + 2 * tig;
                float v0 = acc[mt][nt][2 * i + 0] + bias[col];
                float v1 = acc[mt][nt][2 * i + 1] + bias[col + 1];
                if (res) {
                    const float* rp = res + (size_t)row * Nc + col;
                    v0 += rp[0]; v1 += rp[1];
                }
                if (do_gelu) {
                    v0 = v0 * normcdff(v0);
                    v1 = v1 * normcdff(v1);
                }
                if (Ch) {
                    *(__half2*)(Ch + (size_t)row * Nc + col) = __floats2half2_rn(v0, v1);
                } else {
                    *(float2*)(Cf + (size_t)row * Nc + col) = make_float2(v0, v1);
                }
            }
        }
    }
}

// ---------------------------------------------------------------------------
// Fused window attention: fp32 math, fp16 output (feeds proj GEMM)
// ---------------------------------------------------------------------------
__global__ __launch_bounds__(128) void attn_kernel(
    const float* __restrict__ qkv, const float* __restrict__ rel_bias,
    __half* __restrict__ ao)
{
    int w = blockIdx.x;          // 0..1023
    int head = blockIdx.y;       // 0..15
    int b  = w >> 6;
    int wi = w & 63;
    int wr = wi >> 3;
    int wc = wi & 7;
    int tid = threadIdx.x;

    __shared__ float qs[N_][HD_];
    __shared__ float kT[HD_][N_];
    __shared__ float vT[HD_][N_];
    __shared__ float S [N_][N_];

    int base_col = head * HD_;

    for (int idx = tid; idx < N_ * 8; idx += 128) {
        int n = idx >> 3, f = (idx & 7) * 4;
        int ir = n / 7, ic = n - (n / 7) * 7;
        size_t row = (size_t)(b * 56 + wr * 7 + ir) * 56 + (wc * 7 + ic);
        size_t off = row * QKVC_ + base_col + f;
        float4 qv = *(const float4*)(qkv + off);
        *(float4*)&qs[n][f] = qv;
        float4 kv = *(const float4*)(qkv + off + 512);
        kT[f + 0][n] = kv.x; kT[f + 1][n] = kv.y;
        kT[f + 2][n] = kv.z; kT[f + 3][n] = kv.w;
        float4 vv = *(const float4*)(qkv + off + 1024);
        vT[f + 0][n] = vv.x; vT[f + 1][n] = vv.y;
        vT[f + 2][n] = vv.z; vT[f + 3][n] = vv.w;
    }
    __syncthreads();

    const float* rb = rel_bias + head * (N_ * N_);
    for (int idx = tid; idx < N_ * N_; idx += 128) {
        int i = idx / N_, j = idx - i * N_;
        float s = 0.0f;
        #pragma unroll
        for (int d = 0; d < HD_; d++) s = fmaf(qs[i][d], kT[d][j], s);
        S[i][j] = s * SCALE_ + rb[idx];
    }
    __syncthreads();

    int warp = tid >> 5, lane = tid & 31;
    for (int i = warp; i < N_; i += 4) {
        float m = -1e30f;
        for (int j = lane; j < N_; j += 32) m = fmaxf(m, S[i][j]);
        #pragma unroll
        for (int o = 16; o; o >>= 1) m = fmaxf(m, __shfl_xor_sync(0xffffffffu, m, o));
        float sum = 0.0f;
        for (int j = lane; j < N_; j += 32) {
            float e = __expf(S[i][j] - m);
            S[i][j] = e;
            sum += e;
        }
        #pragma unroll
        for (int o = 16; o; o >>= 1) sum += __shfl_xor_sync(0xffffffffu, sum, o);
        float inv = 1.0f / sum;
        for (int j = lane; j < N_; j += 32) S[i][j] *= inv;
    }
    __syncthreads();

    for (int idx = tid; idx < N_ * HD_; idx += 128) {
        int i = idx >> 5, d = idx & 31;
        float s = 0.0f;
        #pragma unroll
        for (int j = 0; j < N_; j++) s = fmaf(S[i][j], vT[d][j], s);
        int ir = i / 7, ic = i - (i / 7) * 7;
        size_t row = (size_t)(b * 56 + wr * 7 + ir) * 56 + (wc * 7 + ic);
        ao[row * C_ + base_col + d] = __float2half_rn(s);
    }
}

// ---------------------------------------------------------------------------
// Launch
// ---------------------------------------------------------------------------
extern "C" void kernel_launch(void* const* d_in, const int* in_sizes, int n_in,
                              void* d_out, int out_size)
{
    const float* x    = (const float*)d_in[0];
    const float* Wq   = (const float*)d_in[1];
    const float* bq   = (const float*)d_in[2];
    const float* Wk   = (const float*)d_in[3];
    const float* bk   = (const float*)d_in[4];
    const float* Wv   = (const float*)d_in[5];
    const float* bv   = (const float*)d_in[6];
    const float* Wp   = (const float*)d_in[7];
    const float* bp   = (const float*)d_in[8];
    const float* rel  = (const float*)d_in[9];
    const float* g1   = (const float*)d_in[10];
    const float* b1   = (const float*)d_in[11];
    const float* g2   = (const float*)d_in[12];
    const float* b2   = (const float*)d_in[13];
    const float* W1   = (const float*)d_in[14];
    const float* bfc1 = (const float*)d_in[15];
    const float* W2   = (const float*)d_in[16];
    const float* bfc2 = (const float*)d_in[17];
    float* out = (float*)d_out;

    __half *h, *ao, *hid, *wtqkv, *wtp, *wt1, *wt2;
    float *qkv, *x2, *bqkv;
    cudaGetSymbolAddress((void**)&h,     g_h);
    cudaGetSymbolAddress((void**)&qkv,   g_qkv);
    cudaGetSymbolAddress((void**)&ao,    g_ao);
    cudaGetSymbolAddress((void**)&x2,    g_x2);
    cudaGetSymbolAddress((void**)&hid,   g_hid);
    cudaGetSymbolAddress((void**)&wtqkv, g_wtqkv);
    cudaGetSymbolAddress((void**)&wtp,   g_wtp);
    cudaGetSymbolAddress((void**)&wt1,   g_wt1);
    cudaGetSymbolAddress((void**)&wt2,   g_wt2);
    cudaGetSymbolAddress((void**)&bqkv,  g_bqkv);

    // 0. Weight transposes (K-major, fp16) + bias packing
    dim3 tb(32, 8);
    transpose_kernel<<<dim3(C_ / 32, C_ / 32), tb>>>(Wq, wtqkv,             C_, C_);
    transpose_kernel<<<dim3(C_ / 32, C_ / 32), tb>>>(Wk, wtqkv + 512 * C_,  C_, C_);
    transpose_kernel<<<dim3(C_ / 32, C_ / 32), tb>>>(Wv, wtqkv + 1024 * C_, C_, C_);
    transpose_kernel<<<dim3(C_ / 32, C_ / 32), tb>>>(Wp, wtp, C_, C_);
    transpose_kernel<<<dim3(HID_ / 32, C_ / 32), tb>>>(W1, wt1, C_, HID_);
    transpose_kernel<<<dim3(C_ / 32, HID_ / 32), tb>>>(W2, wt2, HID_, C_);
    pack_bias_kernel<<<6, 256>>>(bq, bk, bv, bqkv);

    // 1. LN1 -> h (fp16)
    ln_kernel<<<ROWS_, 128>>>(x, g1, b1, h);

    // 2. Fused QKV projection (N = 1536) -> qkv (fp32)
    mma_gemm<<<dim3(QKVC_ / GBN, ROWS_ / GBM), 256>>>(
        h, wtqkv, bqkv, nullptr, qkv, nullptr, ROWS_, QKVC_, C_, 0);

    // 3. Windowed attention -> ao (fp16)
    attn_kernel<<<dim3(B_ * NW_, NH_), 128>>>(qkv, rel, ao);

    // 4. Output projection + residual: x2 = x + ao @ Wp + bp (fp32)
    mma_gemm<<<dim3(C_ / GBN, ROWS_ / GBM), 256>>>(
        ao, wtp, bp, x, x2, nullptr, ROWS_, C_, C_, 0);

    // 5. LN2 -> h (fp16)
    ln_kernel<<<ROWS_, 128>>>(x2, g2, b2, h);

    // 6. MLP fc1 + exact GELU -> hid (fp16)
    mma_gemm<<<dim3(HID_ / GBN, ROWS_ / GBM), 256>>>(
        h, wt1, bfc1, nullptr, nullptr, hid, ROWS_, HID_, C_, 1);

    // 7. MLP fc2 + residual -> out (fp32)
    mma_gemm<<<dim3(C_ / GBN, ROWS_ / GBM), 256>>>(
        hid, wt2, bfc2, x2, out, nullptr, ROWS_, C_, HID_, 0);
}